// round 1
// baseline (speedup 1.0000x reference)
#include <cuda_runtime.h>

#define NB 16
#define NT 512
#define ND 256
#define NH 4
#define NHD 64
#define NTAG 64
#define NBT (NB*NT)   // 8192

// ---------------- device scratch (no allocs allowed) ----------------
__device__ float g_q[64*512*64];     // (b*4+h, t, d), pre-scaled by 1/8
__device__ float g_k[64*512*64];
__device__ float g_v[64*512*64];
__device__ float g_s[64u*512u*512u]; // scores -> probs (in-place softmax)
__device__ float g_o[NBT*ND];        // merged-head attention output (b*t, D)
__device__ float g_ao[NBT*ND];       // after Wo projection
__device__ float g_A[512*16*16];     // (t, b, gate*4+w): precomputed angles (incl bias+theta)
__device__ float g_hs[512*16*4];     // lstm hidden states (t, b, w)

__device__ __forceinline__ float sigf(float x) {
    return __fdividef(1.f, 1.f + __expf(-x));
}

// =====================================================================
// K1: fused embedding gather + QKV projection.
// M=8192 rows (b*t), N=768 (q|k|v each 256), K=256.
// =====================================================================
__global__ void k_qkv(const int* __restrict__ sent, const float* __restrict__ emb,
                      const float* __restrict__ Wq, const float* __restrict__ bq,
                      const float* __restrict__ Wk, const float* __restrict__ bk,
                      const float* __restrict__ Wv, const float* __restrict__ bv)
{
    __shared__ __align__(16) float As[16][68];
    __shared__ __align__(16) float Bs[16][68];
    __shared__ int sidx[64];
    const int m0 = blockIdx.x * 64;
    const int n0 = blockIdx.y * 64;          // 0..767
    const int which = n0 >> 8;               // 0=q,1=k,2=v (tiles align)
    const int wn0 = n0 & 255;
    const float* W = (which == 0) ? Wq : (which == 1) ? Wk : Wv;
    const float* bias = (which == 0) ? bq : (which == 1) ? bk : bv;

    const int tid = threadIdx.x;
    if (tid < 64) sidx[tid] = sent[m0 + tid];
    __syncthreads();

    const int lm = tid >> 2;
    const int lk = (tid & 3) * 4;
    const int ty = tid >> 4, tx = tid & 15;
    float acc[4][4] = {};

    for (int k0 = 0; k0 < 256; k0 += 16) {
        float4 a4 = *(const float4*)(emb + (size_t)sidx[lm] * 256 + k0 + lk);
        float4 b4 = *(const float4*)(W + (size_t)(wn0 + lm) * 256 + k0 + lk);
        As[lk + 0][lm] = a4.x; As[lk + 1][lm] = a4.y; As[lk + 2][lm] = a4.z; As[lk + 3][lm] = a4.w;
        Bs[lk + 0][lm] = b4.x; Bs[lk + 1][lm] = b4.y; Bs[lk + 2][lm] = b4.z; Bs[lk + 3][lm] = b4.w;
        __syncthreads();
#pragma unroll
        for (int k = 0; k < 16; ++k) {
            float4 av = *(const float4*)&As[k][ty * 4];
            float4 bv4 = *(const float4*)&Bs[k][tx * 4];
            float ar[4] = {av.x, av.y, av.z, av.w};
            float br[4] = {bv4.x, bv4.y, bv4.z, bv4.w};
#pragma unroll
            for (int i = 0; i < 4; ++i)
#pragma unroll
                for (int j = 0; j < 4; ++j) acc[i][j] += ar[i] * br[j];
        }
        __syncthreads();
    }

    float* dst = (which == 0) ? g_q : (which == 1) ? g_k : g_v;
    const float qs = (which == 0) ? 0.125f : 1.0f;   // 1/sqrt(64) folded into q
#pragma unroll
    for (int i = 0; i < 4; ++i) {
        const int r = m0 + ty * 4 + i;
        const int b = r >> 9, t = r & 511;
#pragma unroll
        for (int j = 0; j < 4; ++j) {
            const int wn = wn0 + tx * 4 + j;
            const int h = wn >> 6, d = wn & 63;
            float v = (acc[i][j] + bias[wn]) * qs;
            dst[(((size_t)(b * 4 + h)) * 512 + t) * 64 + d] = v;
        }
    }
}

// =====================================================================
// K2: scores[bh] = Q(512x64) * K^T   (q already scaled)
// =====================================================================
__global__ void k_scores()
{
    __shared__ __align__(16) float Qs[64][68];
    __shared__ __align__(16) float Ks[64][68];
    const int bh = blockIdx.z;
    const int m0 = blockIdx.x * 64;
    const int n0 = blockIdx.y * 64;
    const float* Q = g_q + (size_t)bh * 512 * 64;
    const float* K = g_k + (size_t)bh * 512 * 64;

    const int tid = threadIdx.x;
    const int lm = tid >> 2;
    const int lk = (tid & 3) * 4;
#pragma unroll
    for (int c = 0; c < 64; c += 16) {
        float4 q4 = *(const float4*)(Q + (size_t)(m0 + lm) * 64 + lk + c);
        Qs[lk + c + 0][lm] = q4.x; Qs[lk + c + 1][lm] = q4.y;
        Qs[lk + c + 2][lm] = q4.z; Qs[lk + c + 3][lm] = q4.w;
        float4 k4 = *(const float4*)(K + (size_t)(n0 + lm) * 64 + lk + c);
        Ks[lk + c + 0][lm] = k4.x; Ks[lk + c + 1][lm] = k4.y;
        Ks[lk + c + 2][lm] = k4.z; Ks[lk + c + 3][lm] = k4.w;
    }
    __syncthreads();

    const int ty = tid >> 4, tx = tid & 15;
    float acc[4][4] = {};
#pragma unroll 16
    for (int k = 0; k < 64; ++k) {
        float4 av = *(const float4*)&Qs[k][ty * 4];
        float4 bv4 = *(const float4*)&Ks[k][tx * 4];
        float ar[4] = {av.x, av.y, av.z, av.w};
        float br[4] = {bv4.x, bv4.y, bv4.z, bv4.w};
#pragma unroll
        for (int i = 0; i < 4; ++i)
#pragma unroll
            for (int j = 0; j < 4; ++j) acc[i][j] += ar[i] * br[j];
    }
#pragma unroll
    for (int i = 0; i < 4; ++i)
#pragma unroll
        for (int j = 0; j < 4; ++j)
            g_s[((size_t)bh * 512 + m0 + ty * 4 + i) * 512 + n0 + tx * 4 + j] = acc[i][j];
}

// =====================================================================
// K3: row softmax over 512 (warp per row, in-place on g_s)
// =====================================================================
__global__ void k_softmax()
{
    const int row = blockIdx.x * 8 + (threadIdx.x >> 5);
    const int lane = threadIdx.x & 31;
    float* p = g_s + (size_t)row * 512;
    float4 v[4];
#pragma unroll
    for (int i = 0; i < 4; ++i) v[i] = *(const float4*)(p + i * 128 + lane * 4);
    float m = -1e30f;
#pragma unroll
    for (int i = 0; i < 4; ++i) {
        m = fmaxf(m, fmaxf(fmaxf(v[i].x, v[i].y), fmaxf(v[i].z, v[i].w)));
    }
#pragma unroll
    for (int o = 16; o >= 1; o >>= 1) m = fmaxf(m, __shfl_xor_sync(0xffffffffu, m, o));
    float s = 0.f;
#pragma unroll
    for (int i = 0; i < 4; ++i) {
        v[i].x = __expf(v[i].x - m); v[i].y = __expf(v[i].y - m);
        v[i].z = __expf(v[i].z - m); v[i].w = __expf(v[i].w - m);
        s += v[i].x + v[i].y + v[i].z + v[i].w;
    }
#pragma unroll
    for (int o = 16; o >= 1; o >>= 1) s += __shfl_xor_sync(0xffffffffu, s, o);
    const float inv = __fdividef(1.f, s);
#pragma unroll
    for (int i = 0; i < 4; ++i) {
        v[i].x *= inv; v[i].y *= inv; v[i].z *= inv; v[i].w *= inv;
        *(float4*)(p + i * 128 + lane * 4) = v[i];
    }
}

// =====================================================================
// K4: o[bh] = P(512x512) * V(512x64), stored merged-head (b,t,D)
// =====================================================================
__global__ void k_av()
{
    __shared__ __align__(16) float Ps[32][68];
    __shared__ __align__(16) float Vs[32][68];
    const int bh = blockIdx.y;
    const int m0 = blockIdx.x * 64;
    const float* P = g_s + (size_t)bh * 512 * 512;
    const float* V = g_v + (size_t)bh * 512 * 64;

    const int tid = threadIdx.x;
    const int lm = tid >> 2;
    const int lk = (tid & 3) * 4;
    const int vr = tid >> 4;
    const int vc = (tid & 15) * 4;
    const int ty = tid >> 4, tx = tid & 15;
    float acc[4][4] = {};

    for (int k0 = 0; k0 < 512; k0 += 32) {
#pragma unroll
        for (int c = 0; c < 32; c += 16) {
            float4 p4 = *(const float4*)(P + (size_t)(m0 + lm) * 512 + k0 + lk + c);
            Ps[lk + c + 0][lm] = p4.x; Ps[lk + c + 1][lm] = p4.y;
            Ps[lk + c + 2][lm] = p4.z; Ps[lk + c + 3][lm] = p4.w;
            float4 v4 = *(const float4*)(V + (size_t)(k0 + vr + c) * 64 + vc);
            *(float4*)&Vs[vr + c][vc] = v4;
        }
        __syncthreads();
#pragma unroll
        for (int k = 0; k < 32; ++k) {
            float4 av = *(const float4*)&Ps[k][ty * 4];
            float4 bv4 = *(const float4*)&Vs[k][tx * 4];
            float ar[4] = {av.x, av.y, av.z, av.w};
            float br[4] = {bv4.x, bv4.y, bv4.z, bv4.w};
#pragma unroll
            for (int i = 0; i < 4; ++i)
#pragma unroll
                for (int j = 0; j < 4; ++j) acc[i][j] += ar[i] * br[j];
        }
        __syncthreads();
    }
    const int b = bh >> 2, h = bh & 3;
#pragma unroll
    for (int i = 0; i < 4; ++i) {
        const int t = m0 + ty * 4 + i;
#pragma unroll
        for (int j = 0; j < 4; ++j)
            g_o[((size_t)(b * 512 + t)) * 256 + h * 64 + tx * 4 + j] = acc[i][j];
    }
}

// =====================================================================
// K5: attn_out = o @ Wo^T + bo   (M=8192, N=256, K=256)
// =====================================================================
__global__ void k_wo(const float* __restrict__ Wo, const float* __restrict__ bo)
{
    __shared__ __align__(16) float As[16][68];
    __shared__ __align__(16) float Bs[16][68];
    const int m0 = blockIdx.x * 64;
    const int n0 = blockIdx.y * 64;
    const int tid = threadIdx.x;
    const int lm = tid >> 2;
    const int lk = (tid & 3) * 4;
    const int ty = tid >> 4, tx = tid & 15;
    float acc[4][4] = {};

    for (int k0 = 0; k0 < 256; k0 += 16) {
        float4 a4 = *(const float4*)(g_o + (size_t)(m0 + lm) * 256 + k0 + lk);
        float4 b4 = *(const float4*)(Wo + (size_t)(n0 + lm) * 256 + k0 + lk);
        As[lk + 0][lm] = a4.x; As[lk + 1][lm] = a4.y; As[lk + 2][lm] = a4.z; As[lk + 3][lm] = a4.w;
        Bs[lk + 0][lm] = b4.x; Bs[lk + 1][lm] = b4.y; Bs[lk + 2][lm] = b4.z; Bs[lk + 3][lm] = b4.w;
        __syncthreads();
#pragma unroll
        for (int k = 0; k < 16; ++k) {
            float4 av = *(const float4*)&As[k][ty * 4];
            float4 bv4 = *(const float4*)&Bs[k][tx * 4];
            float ar[4] = {av.x, av.y, av.z, av.w};
            float br[4] = {bv4.x, bv4.y, bv4.z, bv4.w};
#pragma unroll
            for (int i = 0; i < 4; ++i)
#pragma unroll
                for (int j = 0; j < 4; ++j) acc[i][j] += ar[i] * br[j];
        }
        __syncthreads();
    }
#pragma unroll
    for (int i = 0; i < 4; ++i) {
        const int r = m0 + ty * 4 + i;
#pragma unroll
        for (int j = 0; j < 4; ++j) {
            const int n = n0 + tx * 4 + j;
            g_ao[(size_t)r * 256 + n] = acc[i][j] + bo[n];
        }
    }
}

// =====================================================================
// K6: gate angle precompute: A[t][b][g*4+w] = attn_out . Wg[w,:256] + bg[w] + thg[w]
// =====================================================================
__global__ void k_gates(const float* __restrict__ Wf, const float* __restrict__ bf, const float* __restrict__ thf,
                        const float* __restrict__ Wi, const float* __restrict__ bi, const float* __restrict__ thi,
                        const float* __restrict__ Wg_, const float* __restrict__ bg, const float* __restrict__ thg,
                        const float* __restrict__ Wo2, const float* __restrict__ bo2, const float* __restrict__ tho)
{
    __shared__ float sW[256][16];
    const int tid = threadIdx.x;
    for (int e = tid; e < 4096; e += 256) {
        const int k = e >> 4, n = e & 15;
        const int gg = n >> 2, w = n & 3;
        const float* Wsel = (gg == 0) ? Wf : (gg == 1) ? Wi : (gg == 2) ? Wg_ : Wo2;
        sW[k][n] = Wsel[w * 260 + k];
    }
    __syncthreads();

    const int n = tid & 15;
    const int gg = n >> 2, w = n & 3;
    const float bn = ((gg == 0) ? bf[w] : (gg == 1) ? bi[w] : (gg == 2) ? bg[w] : bo2[w]) +
                     ((gg == 0) ? thf[w] : (gg == 1) ? thi[w] : (gg == 2) ? thg[w] : tho[w]);
    const int r = blockIdx.x * 16 + (tid >> 4);
    const float* a = g_ao + (size_t)r * 256;
    float acc = 0.f;
#pragma unroll 8
    for (int k = 0; k < 256; k += 4) {
        float4 a4 = *(const float4*)(a + k);
        acc += a4.x * sW[k + 0][n] + a4.y * sW[k + 1][n] + a4.z * sW[k + 2][n] + a4.w * sW[k + 3][n];
    }
    const int b = r >> 9, t = r & 511;
    g_A[(t * 16 + b) * 16 + n] = acc + bn;
}

// =====================================================================
// K7: sequential qLSTM scan. 1 block, 64 threads = (16 batch x 4 gates).
// Quantum layer closed form: c_w = cos(angle_w + theta_w),
//   Z0=c1c2c3, Z1=c0c1, Z2=c0c1c2, Z3=c0c1c2c3
// =====================================================================
__global__ void k_lstm(const float* __restrict__ Wf, const float* __restrict__ Wi,
                       const float* __restrict__ Wg_, const float* __restrict__ Wo2)
{
    const int lane = threadIdx.x & 31;
    const int warp = threadIdx.x >> 5;
    const int g = lane >> 3;
    const int b8 = lane & 7;
    const int b = warp * 8 + b8;
    const float* Wsel = (g == 0) ? Wf : (g == 1) ? Wi : (g == 2) ? Wg_ : Wo2;

    float Wh[4][4];
#pragma unroll
    for (int w = 0; w < 4; ++w)
#pragma unroll
        for (int j = 0; j < 4; ++j) Wh[w][j] = Wsel[w * 260 + 256 + j];

    const float zscale = (g == 2) ? 2.f : 1.f;   // tanh(z)=2*sig(2z)-1 for gate g
    const float ascale = (g == 2) ? 2.f : 1.f;
    const float abias  = (g == 2) ? -1.f : 0.f;

    float cx0 = 0.f, cx1 = 0.f, cx2 = 0.f, cx3 = 0.f;
    float h0 = 0.f, h1 = 0.f, h2 = 0.f, h3 = 0.f;

    float4 a = *(const float4*)(g_A + ((size_t)0 * 16 + b) * 16 + g * 4);
    for (int t = 0; t < 512; ++t) {
        const int tn = (t + 1 < 512) ? (t + 1) : 511;
        float4 anext = *(const float4*)(g_A + ((size_t)tn * 16 + b) * 16 + g * 4);

        float an0 = a.x + Wh[0][0] * h0 + Wh[0][1] * h1 + Wh[0][2] * h2 + Wh[0][3] * h3;
        float an1 = a.y + Wh[1][0] * h0 + Wh[1][1] * h1 + Wh[1][2] * h2 + Wh[1][3] * h3;
        float an2 = a.z + Wh[2][0] * h0 + Wh[2][1] * h1 + Wh[2][2] * h2 + Wh[2][3] * h3;
        float an3 = a.w + Wh[3][0] * h0 + Wh[3][1] * h1 + Wh[3][2] * h2 + Wh[3][3] * h3;

        float c0 = __cosf(an0), c1 = __cosf(an1), c2 = __cosf(an2), c3 = __cosf(an3);
        float z1 = c0 * c1;
        float c12 = c1 * c2;
        float z0 = c12 * c3;
        float z2 = z1 * c2;
        float z3 = z2 * c3;

        float act0 = ascale * sigf(zscale * z0) + abias;
        float act1 = ascale * sigf(zscale * z1) + abias;
        float act2 = ascale * sigf(zscale * z2) + abias;
        float act3 = ascale * sigf(zscale * z3) + abias;

        const unsigned mask = 0xffffffffu;
        float f0 = __shfl_sync(mask, act0, b8),      f1 = __shfl_sync(mask, act1, b8);
        float f2 = __shfl_sync(mask, act2, b8),      f3 = __shfl_sync(mask, act3, b8);
        float i0 = __shfl_sync(mask, act0, 8 + b8),  i1 = __shfl_sync(mask, act1, 8 + b8);
        float i2 = __shfl_sync(mask, act2, 8 + b8),  i3 = __shfl_sync(mask, act3, 8 + b8);
        float gg0 = __shfl_sync(mask, act0, 16 + b8), gg1 = __shfl_sync(mask, act1, 16 + b8);
        float gg2 = __shfl_sync(mask, act2, 16 + b8), gg3 = __shfl_sync(mask, act3, 16 + b8);
        float o0 = __shfl_sync(mask, act0, 24 + b8), o1 = __shfl_sync(mask, act1, 24 + b8);
        float o2 = __shfl_sync(mask, act2, 24 + b8), o3 = __shfl_sync(mask, act3, 24 + b8);

        cx0 = f0 * cx0 + i0 * gg0;
        cx1 = f1 * cx1 + i1 * gg1;
        cx2 = f2 * cx2 + i2 * gg2;
        cx3 = f3 * cx3 + i3 * gg3;

        h0 = o0 * (2.f * sigf(2.f * cx0) - 1.f);
        h1 = o1 * (2.f * sigf(2.f * cx1) - 1.f);
        h2 = o2 * (2.f * sigf(2.f * cx2) - 1.f);
        h3 = o3 * (2.f * sigf(2.f * cx3) - 1.f);

        if (g == 0) *(float4*)(g_hs + ((size_t)t * 16 + b) * 4) = make_float4(h0, h1, h2, h3);
        a = anext;
    }
}

// =====================================================================
// K8: logits = h @ Wt^T + bt; log_softmax over 64 tags. Warp per row.
// =====================================================================
__global__ void k_logits(const float* __restrict__ Wt, const float* __restrict__ bt,
                         float* __restrict__ out)
{
    const int row = blockIdx.x * 8 + (threadIdx.x >> 5);
    const int lane = threadIdx.x & 31;
    const int b = row >> 9, t = row & 511;
    float4 h = *(const float4*)(g_hs + ((size_t)t * 16 + b) * 4);

    const int j0 = lane, j1 = lane + 32;
    float4 w0 = *(const float4*)(Wt + j0 * 4);
    float4 w1 = *(const float4*)(Wt + j1 * 4);
    float l0 = bt[j0] + h.x * w0.x + h.y * w0.y + h.z * w0.z + h.w * w0.w;
    float l1 = bt[j1] + h.x * w1.x + h.y * w1.y + h.z * w1.z + h.w * w1.w;

    float m = fmaxf(l0, l1);
#pragma unroll
    for (int o = 16; o >= 1; o >>= 1) m = fmaxf(m, __shfl_xor_sync(0xffffffffu, m, o));
    float s = __expf(l0 - m) + __expf(l1 - m);
#pragma unroll
    for (int o = 16; o >= 1; o >>= 1) s += __shfl_xor_sync(0xffffffffu, s, o);
    const float lse = m + logf(s);
    out[(size_t)row * 64 + j0] = l0 - lse;
    out[(size_t)row * 64 + j1] = l1 - lse;
}

// =====================================================================
extern "C" void kernel_launch(void* const* d_in, const int* in_sizes, int n_in,
                              void* d_out, int out_size)
{
    const int*   sent = (const int*)d_in[0];
    const float* emb  = (const float*)d_in[1];
    const float* Wq = (const float*)d_in[2];  const float* bq = (const float*)d_in[3];
    const float* Wk = (const float*)d_in[4];  const float* bk = (const float*)d_in[5];
    const float* Wv = (const float*)d_in[6];  const float* bv = (const float*)d_in[7];
    const float* Wo = (const float*)d_in[8];  const float* bo = (const float*)d_in[9];
    const float* Wf = (const float*)d_in[10]; const float* bf = (const float*)d_in[11]; const float* thf = (const float*)d_in[12];
    const float* Wi = (const float*)d_in[13]; const float* bi = (const float*)d_in[14]; const float* thi = (const float*)d_in[15];
    const float* Wg = (const float*)d_in[16]; const float* bg = (const float*)d_in[17]; const float* thg = (const float*)d_in[18];
    const float* Wo2= (const float*)d_in[19]; const float* bo2= (const float*)d_in[20]; const float* tho = (const float*)d_in[21];
    const float* Wt = (const float*)d_in[22]; const float* bt = (const float*)d_in[23];
    float* out = (float*)d_out;

    k_qkv<<<dim3(128, 12), 256>>>(sent, emb, Wq, bq, Wk, bk, Wv, bv);
    k_scores<<<dim3(8, 8, 64), 256>>>();
    k_softmax<<<4096, 256>>>();
    k_av<<<dim3(8, 64), 256>>>();
    k_wo<<<dim3(128, 4), 256>>>(Wo, bo);
    k_gates<<<512, 256>>>(Wf, bf, thf, Wi, bi, thi, Wg, bg, thg, Wo2, bo2, tho);
    k_lstm<<<1, 64>>>(Wf, Wi, Wg, Wo2);
    k_logits<<<1024, 256>>>(Wt, bt, out);
}

// round 2
// speedup vs baseline: 1.0330x; 1.0330x over previous
#include <cuda_runtime.h>

// ---------------- device scratch (no allocs allowed) ----------------
__device__ float g_q[8192*256];   // (b*t, h*64+d), q pre-scaled by 1/8
__device__ float g_k[8192*256];
__device__ float g_v[8192*256];
__device__ float g_o[8192*256];   // attention output (pre-Wo), merged heads
__device__ float g_Wc[16*256];    // combined gate weights (Wgate[:, :256] @ Wo)
__device__ float g_bc[16];        // combined gate bias (+theta)
__device__ float g_A[512*16*16];  // (t, b, gate*4+w) precomputed angles
__device__ float g_hs[512*16*4];  // lstm hidden states (t, b, w)

__device__ __forceinline__ float sigf(float x) {
    return __fdividef(1.f, 1.f + __expf(-x));
}

// =====================================================================
// K1: fused embedding gather + QKV projection.
// M=8192 (b*t), N=768 (q|k|v each 256), K=256. 128x128 tiles, 8x8 micro.
// =====================================================================
__global__ void k_qkv(const int* __restrict__ sent, const float* __restrict__ emb,
                      const float* __restrict__ Wq, const float* __restrict__ bq,
                      const float* __restrict__ Wk, const float* __restrict__ bk,
                      const float* __restrict__ Wv, const float* __restrict__ bv)
{
    __shared__ __align__(16) float As[16][132];
    __shared__ __align__(16) float Bs[16][132];
    __shared__ int sidx[128];
    const int m0 = blockIdx.x * 128;
    const int n0 = blockIdx.y * 128;          // 0..767
    const int which = n0 >> 8;                // 0=q,1=k,2=v
    const int wn0 = n0 & 255;                 // 0 or 128
    const float* W = (which == 0) ? Wq : (which == 1) ? Wk : Wv;
    const float* bias = (which == 0) ? bq : (which == 1) ? bk : bv;

    const int tid = threadIdx.x;
    if (tid < 128) sidx[tid] = sent[m0 + tid];
    __syncthreads();

    const int lm = tid >> 1;          // 0..127
    const int lk = (tid & 1) * 8;     // 0 or 8
    const int ty = tid >> 4, tx = tid & 15;
    float acc[8][8] = {};

    for (int k0 = 0; k0 < 256; k0 += 16) {
        const float* arow = emb + (size_t)sidx[lm] * 256 + k0 + lk;
        float4 a0 = *(const float4*)arow;
        float4 a1 = *(const float4*)(arow + 4);
        const float* brow = W + (size_t)(wn0 + lm) * 256 + k0 + lk;
        float4 b0 = *(const float4*)brow;
        float4 b1 = *(const float4*)(brow + 4);
        As[lk + 0][lm] = a0.x; As[lk + 1][lm] = a0.y; As[lk + 2][lm] = a0.z; As[lk + 3][lm] = a0.w;
        As[lk + 4][lm] = a1.x; As[lk + 5][lm] = a1.y; As[lk + 6][lm] = a1.z; As[lk + 7][lm] = a1.w;
        Bs[lk + 0][lm] = b0.x; Bs[lk + 1][lm] = b0.y; Bs[lk + 2][lm] = b0.z; Bs[lk + 3][lm] = b0.w;
        Bs[lk + 4][lm] = b1.x; Bs[lk + 5][lm] = b1.y; Bs[lk + 6][lm] = b1.z; Bs[lk + 7][lm] = b1.w;
        __syncthreads();
#pragma unroll
        for (int k = 0; k < 16; ++k) {
            float4 aA = *(const float4*)&As[k][ty * 4];
            float4 aB = *(const float4*)&As[k][64 + ty * 4];
            float4 bA = *(const float4*)&Bs[k][tx * 4];
            float4 bB = *(const float4*)&Bs[k][64 + tx * 4];
            float ar[8] = {aA.x, aA.y, aA.z, aA.w, aB.x, aB.y, aB.z, aB.w};
            float br[8] = {bA.x, bA.y, bA.z, bA.w, bB.x, bB.y, bB.z, bB.w};
#pragma unroll
            for (int i = 0; i < 8; ++i)
#pragma unroll
                for (int j = 0; j < 8; ++j) acc[i][j] += ar[i] * br[j];
        }
        __syncthreads();
    }

    float* dst = (which == 0) ? g_q : (which == 1) ? g_k : g_v;
    const float qs = (which == 0) ? 0.125f : 1.0f;   // 1/sqrt(64) folded into q
#pragma unroll
    for (int hi = 0; hi < 2; ++hi)
#pragma unroll
        for (int i = 0; i < 4; ++i) {
            const int r = m0 + hi * 64 + ty * 4 + i;
#pragma unroll
            for (int hj = 0; hj < 2; ++hj) {
                const int cn = wn0 + hj * 64 + tx * 4;
                float4 v;
                v.x = (acc[hi * 4 + i][hj * 4 + 0] + bias[cn + 0]) * qs;
                v.y = (acc[hi * 4 + i][hj * 4 + 1] + bias[cn + 1]) * qs;
                v.z = (acc[hi * 4 + i][hj * 4 + 2] + bias[cn + 2]) * qs;
                v.w = (acc[hi * 4 + i][hj * 4 + 3] + bias[cn + 3]) * qs;
                *(float4*)(dst + (size_t)r * 256 + cn) = v;
            }
        }
}

// =====================================================================
// K2: flash attention. block = (64 q-rows, one head). Online softmax.
// grid (8, 64). Scores never touch global memory.
// =====================================================================
__global__ void k_flash()
{
    __shared__ float Qs[64][64];   // [d][row]
    __shared__ float Ks[64][64];   // [d][col]
    __shared__ float Vs[64][64];   // [k][d]
    const int bh = blockIdx.y;
    const int b = bh >> 2, h = bh & 3;
    const int m0 = blockIdx.x * 64;
    const int tid = threadIdx.x;
    const int ty = tid >> 4, tx = tid & 15;
    const float* Q = g_q + ((size_t)(b * 512 + m0)) * 256 + h * 64;
    const float* K = g_k + ((size_t)(b * 512)) * 256 + h * 64;
    const float* V = g_v + ((size_t)(b * 512)) * 256 + h * 64;

    {
        const int lm = tid >> 2, lk = (tid & 3) * 4;
#pragma unroll
        for (int c = 0; c < 64; c += 16) {
            float4 q4 = *(const float4*)(Q + (size_t)lm * 256 + lk + c);
            Qs[lk + c + 0][lm] = q4.x; Qs[lk + c + 1][lm] = q4.y;
            Qs[lk + c + 2][lm] = q4.z; Qs[lk + c + 3][lm] = q4.w;
        }
    }
    float o[4][4] = {};
    float mrow[4] = {-1e30f, -1e30f, -1e30f, -1e30f};
    float lrow[4] = {};
    __syncthreads();

    for (int kk0 = 0; kk0 < 512; kk0 += 64) {
        {
            const int lm = tid >> 2, lk = (tid & 3) * 4;
#pragma unroll
            for (int c = 0; c < 64; c += 16) {
                float4 k4 = *(const float4*)(K + (size_t)(kk0 + lm) * 256 + lk + c);
                Ks[lk + c + 0][lm] = k4.x; Ks[lk + c + 1][lm] = k4.y;
                Ks[lk + c + 2][lm] = k4.z; Ks[lk + c + 3][lm] = k4.w;
            }
            const int vr = tid >> 4, vc = (tid & 15) * 4;
#pragma unroll
            for (int c = 0; c < 64; c += 16)
                *(float4*)&Vs[vr + c][vc] = *(const float4*)(V + (size_t)(kk0 + vr + c) * 256 + vc);
        }
        __syncthreads();

        float s[4][4] = {};
#pragma unroll
        for (int d = 0; d < 64; ++d) {
            float4 qv = *(const float4*)&Qs[d][ty * 4];
            float4 kv = *(const float4*)&Ks[d][tx * 4];
            float qr[4] = {qv.x, qv.y, qv.z, qv.w};
            float kr[4] = {kv.x, kv.y, kv.z, kv.w};
#pragma unroll
            for (int i = 0; i < 4; ++i)
#pragma unroll
                for (int j = 0; j < 4; ++j) s[i][j] += qr[i] * kr[j];
        }

        // online softmax update (row groups = 16-lane segments)
#pragma unroll
        for (int i = 0; i < 4; ++i) {
            float mx = fmaxf(fmaxf(s[i][0], s[i][1]), fmaxf(s[i][2], s[i][3]));
#pragma unroll
            for (int off = 8; off >= 1; off >>= 1)
                mx = fmaxf(mx, __shfl_xor_sync(0xffffffffu, mx, off, 16));
            const float mnew = fmaxf(mrow[i], mx);
            const float alpha = __expf(mrow[i] - mnew);
            mrow[i] = mnew;
            float rs = 0.f;
#pragma unroll
            for (int j = 0; j < 4; ++j) { s[i][j] = __expf(s[i][j] - mnew); rs += s[i][j]; }
#pragma unroll
            for (int off = 8; off >= 1; off >>= 1)
                rs += __shfl_xor_sync(0xffffffffu, rs, off, 16);
            lrow[i] = lrow[i] * alpha + rs;
#pragma unroll
            for (int j = 0; j < 4; ++j) o[i][j] *= alpha;
        }

        // O += P @ V : broadcast P across the 16-lane row group via shfl
#pragma unroll
        for (int k = 0; k < 64; ++k) {
            float4 vv = *(const float4*)&Vs[k][tx * 4];
            const float p0 = __shfl_sync(0xffffffffu, s[0][k & 3], k >> 2, 16);
            const float p1 = __shfl_sync(0xffffffffu, s[1][k & 3], k >> 2, 16);
            const float p2 = __shfl_sync(0xffffffffu, s[2][k & 3], k >> 2, 16);
            const float p3 = __shfl_sync(0xffffffffu, s[3][k & 3], k >> 2, 16);
            o[0][0] += p0 * vv.x; o[0][1] += p0 * vv.y; o[0][2] += p0 * vv.z; o[0][3] += p0 * vv.w;
            o[1][0] += p1 * vv.x; o[1][1] += p1 * vv.y; o[1][2] += p1 * vv.z; o[1][3] += p1 * vv.w;
            o[2][0] += p2 * vv.x; o[2][1] += p2 * vv.y; o[2][2] += p2 * vv.z; o[2][3] += p2 * vv.w;
            o[3][0] += p3 * vv.x; o[3][1] += p3 * vv.y; o[3][2] += p3 * vv.z; o[3][3] += p3 * vv.w;
        }
        __syncthreads();
    }

#pragma unroll
    for (int i = 0; i < 4; ++i) {
        const float inv = __fdividef(1.f, lrow[i]);
        float4 ov = make_float4(o[i][0] * inv, o[i][1] * inv, o[i][2] * inv, o[i][3] * inv);
        *(float4*)(g_o + (size_t)(b * 512 + m0 + ty * 4 + i) * 256 + h * 64 + tx * 4) = ov;
    }
}

// =====================================================================
// K3: fold Wo into the gate projections:
//   Wc[n][c] = sum_d Wgate_n[d] * Wo[d][c];  bc[n] = Wgate_n . bo + b_n + th_n
// =====================================================================
__global__ void k_combine(const float* __restrict__ Wf, const float* __restrict__ bf, const float* __restrict__ thf,
                          const float* __restrict__ Wi, const float* __restrict__ bi, const float* __restrict__ thi,
                          const float* __restrict__ Wg_, const float* __restrict__ bg, const float* __restrict__ thg,
                          const float* __restrict__ Wo2, const float* __restrict__ bo2, const float* __restrict__ tho,
                          const float* __restrict__ Wo, const float* __restrict__ bo)
{
    __shared__ float sWn[16][256];
    const int tid = threadIdx.x;
    for (int e = tid; e < 4096; e += 256) {
        const int n = e >> 8, k = e & 255;
        const int g = n >> 2, w = n & 3;
        const float* Wsel = (g == 0) ? Wf : (g == 1) ? Wi : (g == 2) ? Wg_ : Wo2;
        sWn[n][k] = Wsel[w * 260 + k];
    }
    __syncthreads();

    const int c = tid;
    float acc[16] = {};
    for (int d = 0; d < 256; ++d) {
        const float w = Wo[d * 256 + c];
#pragma unroll
        for (int n = 0; n < 16; ++n) acc[n] += sWn[n][d] * w;
    }
#pragma unroll
    for (int n = 0; n < 16; ++n) g_Wc[n * 256 + c] = acc[n];

    if (tid < 16) {
        const int g = tid >> 2, w = tid & 3;
        float s = ((g == 0) ? bf[w] : (g == 1) ? bi[w] : (g == 2) ? bg[w] : bo2[w]) +
                  ((g == 0) ? thf[w] : (g == 1) ? thi[w] : (g == 2) ? thg[w] : tho[w]);
        for (int d = 0; d < 256; ++d) s += sWn[tid][d] * bo[d];
        g_bc[tid] = s;
    }
}

// =====================================================================
// K4: gate angle precompute directly from g_o with combined weights.
// =====================================================================
__global__ void k_gates()
{
    __shared__ float sW[256][16];
    __shared__ float sb[16];
    const int tid = threadIdx.x;
    for (int e = tid; e < 4096; e += 256) {
        const int k = e >> 4, n = e & 15;
        sW[k][n] = g_Wc[n * 256 + k];
    }
    if (tid < 16) sb[tid] = g_bc[tid];
    __syncthreads();

    const int n = tid & 15;
    const int r = blockIdx.x * 16 + (tid >> 4);
    const float* a = g_o + (size_t)r * 256;
    float acc = 0.f;
#pragma unroll 8
    for (int k = 0; k < 256; k += 4) {
        float4 a4 = *(const float4*)(a + k);
        acc += a4.x * sW[k + 0][n] + a4.y * sW[k + 1][n] + a4.z * sW[k + 2][n] + a4.w * sW[k + 3][n];
    }
    const int b = r >> 9, t = r & 511;
    g_A[(t * 16 + b) * 16 + n] = acc + sb[n];
}

// =====================================================================
// K5: sequential qLSTM scan. 1 block, 64 threads = (16 batch x 4 gates).
// Quantum layer closed form: c_w = cos(angle_w + theta_w),
//   Z0=c1c2c3, Z1=c0c1, Z2=c0c1c2, Z3=c0c1c2c3
// =====================================================================
__global__ void k_lstm(const float* __restrict__ Wf, const float* __restrict__ Wi,
                       const float* __restrict__ Wg_, const float* __restrict__ Wo2)
{
    const int lane = threadIdx.x & 31;
    const int warp = threadIdx.x >> 5;
    const int g = lane >> 3;
    const int b8 = lane & 7;
    const int b = warp * 8 + b8;
    const float* Wsel = (g == 0) ? Wf : (g == 1) ? Wi : (g == 2) ? Wg_ : Wo2;

    float Wh[4][4];
#pragma unroll
    for (int w = 0; w < 4; ++w)
#pragma unroll
        for (int j = 0; j < 4; ++j) Wh[w][j] = Wsel[w * 260 + 256 + j];

    const float zscale = (g == 2) ? 2.f : 1.f;
    const float ascale = (g == 2) ? 2.f : 1.f;
    const float abias  = (g == 2) ? -1.f : 0.f;

    float cx0 = 0.f, cx1 = 0.f, cx2 = 0.f, cx3 = 0.f;
    float h0 = 0.f, h1 = 0.f, h2 = 0.f, h3 = 0.f;

    float4 a = *(const float4*)(g_A + ((size_t)0 * 16 + b) * 16 + g * 4);
    for (int t = 0; t < 512; ++t) {
        const int tn = (t + 1 < 512) ? (t + 1) : 511;
        float4 anext = *(const float4*)(g_A + ((size_t)tn * 16 + b) * 16 + g * 4);

        float an0 = a.x + Wh[0][0] * h0 + Wh[0][1] * h1 + Wh[0][2] * h2 + Wh[0][3] * h3;
        float an1 = a.y + Wh[1][0] * h0 + Wh[1][1] * h1 + Wh[1][2] * h2 + Wh[1][3] * h3;
        float an2 = a.z + Wh[2][0] * h0 + Wh[2][1] * h1 + Wh[2][2] * h2 + Wh[2][3] * h3;
        float an3 = a.w + Wh[3][0] * h0 + Wh[3][1] * h1 + Wh[3][2] * h2 + Wh[3][3] * h3;

        float c0 = __cosf(an0), c1 = __cosf(an1), c2 = __cosf(an2), c3 = __cosf(an3);
        float z1 = c0 * c1;
        float c12 = c1 * c2;
        float z0 = c12 * c3;
        float z2 = z1 * c2;
        float z3 = z2 * c3;

        float act0 = ascale * sigf(zscale * z0) + abias;
        float act1 = ascale * sigf(zscale * z1) + abias;
        float act2 = ascale * sigf(zscale * z2) + abias;
        float act3 = ascale * sigf(zscale * z3) + abias;

        const unsigned mask = 0xffffffffu;
        float f0 = __shfl_sync(mask, act0, b8),      f1 = __shfl_sync(mask, act1, b8);
        float f2 = __shfl_sync(mask, act2, b8),      f3 = __shfl_sync(mask, act3, b8);
        float i0 = __shfl_sync(mask, act0, 8 + b8),  i1 = __shfl_sync(mask, act1, 8 + b8);
        float i2 = __shfl_sync(mask, act2, 8 + b8),  i3 = __shfl_sync(mask, act3, 8 + b8);
        float gg0 = __shfl_sync(mask, act0, 16 + b8), gg1 = __shfl_sync(mask, act1, 16 + b8);
        float gg2 = __shfl_sync(mask, act2, 16 + b8), gg3 = __shfl_sync(mask, act3, 16 + b8);
        float o0 = __shfl_sync(mask, act0, 24 + b8), o1 = __shfl_sync(mask, act1, 24 + b8);
        float o2 = __shfl_sync(mask, act2, 24 + b8), o3 = __shfl_sync(mask, act3, 24 + b8);

        cx0 = f0 * cx0 + i0 * gg0;
        cx1 = f1 * cx1 + i1 * gg1;
        cx2 = f2 * cx2 + i2 * gg2;
        cx3 = f3 * cx3 + i3 * gg3;

        h0 = o0 * (2.f * sigf(2.f * cx0) - 1.f);
        h1 = o1 * (2.f * sigf(2.f * cx1) - 1.f);
        h2 = o2 * (2.f * sigf(2.f * cx2) - 1.f);
        h3 = o3 * (2.f * sigf(2.f * cx3) - 1.f);

        if (g == 0) *(float4*)(g_hs + ((size_t)t * 16 + b) * 4) = make_float4(h0, h1, h2, h3);
        a = anext;
    }
}

// =====================================================================
// K6: logits = h @ Wt^T + bt; log_softmax over 64 tags. Warp per row.
// =====================================================================
__global__ void k_logits(const float* __restrict__ Wt, const float* __restrict__ bt,
                         float* __restrict__ out)
{
    const int row = blockIdx.x * 8 + (threadIdx.x >> 5);
    const int lane = threadIdx.x & 31;
    const int b = row >> 9, t = row & 511;
    float4 h = *(const float4*)(g_hs + ((size_t)t * 16 + b) * 4);

    const int j0 = lane, j1 = lane + 32;
    float4 w0 = *(const float4*)(Wt + j0 * 4);
    float4 w1 = *(const float4*)(Wt + j1 * 4);
    float l0 = bt[j0] + h.x * w0.x + h.y * w0.y + h.z * w0.z + h.w * w0.w;
    float l1 = bt[j1] + h.x * w1.x + h.y * w1.y + h.z * w1.z + h.w * w1.w;

    float m = fmaxf(l0, l1);
#pragma unroll
    for (int o = 16; o >= 1; o >>= 1) m = fmaxf(m, __shfl_xor_sync(0xffffffffu, m, o));
    float s = __expf(l0 - m) + __expf(l1 - m);
#pragma unroll
    for (int o = 16; o >= 1; o >>= 1) s += __shfl_xor_sync(0xffffffffu, s, o);
    const float lse = m + logf(s);
    out[(size_t)row * 64 + j0] = l0 - lse;
    out[(size_t)row * 64 + j1] = l1 - lse;
}

// =====================================================================
extern "C" void kernel_launch(void* const* d_in, const int* in_sizes, int n_in,
                              void* d_out, int out_size)
{
    const int*   sent = (const int*)d_in[0];
    const float* emb  = (const float*)d_in[1];
    const float* Wq = (const float*)d_in[2];  const float* bq = (const float*)d_in[3];
    const float* Wk = (const float*)d_in[4];  const float* bk = (const float*)d_in[5];
    const float* Wv = (const float*)d_in[6];  const float* bv = (const float*)d_in[7];
    const float* Wo = (const float*)d_in[8];  const float* bo = (const float*)d_in[9];
    const float* Wf = (const float*)d_in[10]; const float* bf = (const float*)d_in[11]; const float* thf = (const float*)d_in[12];
    const float* Wi = (const float*)d_in[13]; const float* bi = (const float*)d_in[14]; const float* thi = (const float*)d_in[15];
    const float* Wg = (const float*)d_in[16]; const float* bg = (const float*)d_in[17]; const float* thg = (const float*)d_in[18];
    const float* Wo2= (const float*)d_in[19]; const float* bo2= (const float*)d_in[20]; const float* tho = (const float*)d_in[21];
    const float* Wt = (const float*)d_in[22]; const float* bt = (const float*)d_in[23];
    float* out = (float*)d_out;

    k_qkv<<<dim3(64, 6), 256>>>(sent, emb, Wq, bq, Wk, bk, Wv, bv);
    k_combine<<<1, 256>>>(Wf, bf, thf, Wi, bi, thi, Wg, bg, thg, Wo2, bo2, tho, Wo, bo);
    k_flash<<<dim3(8, 64), 256>>>();
    k_gates<<<512, 256>>>();
    k_lstm<<<1, 64>>>(Wf, Wi, Wg, Wo2);
    k_logits<<<1024, 256>>>(Wt, bt, out);
}